// round 1
// baseline (speedup 1.0000x reference)
#include <cuda_runtime.h>
#include <math.h>

#define DIM     1024
#define HEADS   8
#define DH      64
#define NSEQ    4096
#define BATCH   2
#define TOKENS  (BATCH*NSEQ)     // 8192
#define QKV_N   (3*HEADS*DH)     // 1536
#define AO_N    (HEADS*DH)       // 512

// ---------------- scratch (device globals; no allocations allowed) ----------
__device__ __align__(16) float g_xn[TOKENS * DIM];                 // 32 MB
__device__ __align__(16) float g_q [BATCH*HEADS*NSEQ*DH];          // 16 MB
__device__ __align__(16) float g_k [BATCH*HEADS*NSEQ*DH];          // 16 MB
__device__ __align__(16) float g_v [BATCH*HEADS*NSEQ*DH];          // 16 MB
__device__ __align__(16) float g_ao[TOKENS * AO_N];                // 16 MB

// ---------------- 1) LayerNorm ----------------------------------------------
// one block per token, 256 threads, each thread owns one float4 (1024/256*4)
__global__ void ln_kernel(const float* __restrict__ x,
                          const float* __restrict__ gamma,
                          const float* __restrict__ beta) {
    const int t   = blockIdx.x;
    const int tid = threadIdx.x;
    const float4 v = *(const float4*)(x + (size_t)t * DIM + tid * 4);

    float s  = v.x + v.y + v.z + v.w;
    float s2 = v.x*v.x + v.y*v.y + v.z*v.z + v.w*v.w;
    #pragma unroll
    for (int o = 16; o > 0; o >>= 1) {
        s  += __shfl_down_sync(0xffffffffu, s,  o);
        s2 += __shfl_down_sync(0xffffffffu, s2, o);
    }
    __shared__ float ws[8], ws2[8];
    __shared__ float s_mu, s_rstd;
    const int wid = tid >> 5, lane = tid & 31;
    if (lane == 0) { ws[wid] = s; ws2[wid] = s2; }
    __syncthreads();
    if (tid == 0) {
        float S = 0.f, S2 = 0.f;
        #pragma unroll
        for (int i = 0; i < 8; i++) { S += ws[i]; S2 += ws2[i]; }
        float mu  = S * (1.0f / DIM);
        float var = S2 * (1.0f / DIM) - mu * mu;
        s_mu = mu;
        s_rstd = rsqrtf(var + 1e-5f);
    }
    __syncthreads();
    const float mu = s_mu, rstd = s_rstd;
    const float4 g = *(const float4*)(gamma + tid * 4);
    const float4 b = *(const float4*)(beta  + tid * 4);
    float4 y;
    y.x = (v.x - mu) * rstd * g.x + b.x;
    y.y = (v.y - mu) * rstd * g.y + b.y;
    y.z = (v.z - mu) * rstd * g.z + b.z;
    y.w = (v.w - mu) * rstd * g.w + b.w;
    *(float4*)(g_xn + (size_t)t * DIM + tid * 4) = y;
}

// ---------------- 2)+(4) tiled SGEMM, 128x128x16, 256 thr, 8x8/thread -------
// MODE 0: A=g_xn (lda=1024, K=1024), scatter epilogue -> g_q/g_k/g_v
// MODE 1: A=g_ao (lda=512,  K=512),  plain epilogue -> C (ldc=1024)
template<int MODE>
__global__ void __launch_bounds__(256, 2)
gemm128(const float* __restrict__ B, float* __restrict__ C) {
    constexpr int LDA = (MODE == 0) ? DIM : AO_N;
    constexpr int K   = LDA;
    constexpr int LDB = (MODE == 0) ? QKV_N : DIM;

    __shared__ float As[16][128];   // transposed: As[k][m]
    __shared__ float Bs[16][128];

    const int tid = threadIdx.x;
    const int tx = tid & 15, ty = tid >> 4;
    const int bx = blockIdx.x, by = blockIdx.y;

    const float* A  = (MODE == 0) ? g_xn : g_ao;
    const float* Ab = A + (size_t)by * 128 * LDA;
    const float* Bb = B + bx * 128;

    float acc[8][8];
    #pragma unroll
    for (int i = 0; i < 8; i++)
        #pragma unroll
        for (int j = 0; j < 8; j++) acc[i][j] = 0.f;

    const int arow = tid >> 2, acol = (tid & 3) * 4;     // A: 2 float4 / thread
    const int brow = tid >> 5, bcol = (tid & 31) * 4;    // B: 2 float4 / thread

    for (int k0 = 0; k0 < K; k0 += 16) {
        const float4 a0 = *(const float4*)(Ab + (size_t)arow        * LDA + k0 + acol);
        const float4 a1 = *(const float4*)(Ab + (size_t)(arow + 64) * LDA + k0 + acol);
        const float4 b0 = *(const float4*)(Bb + (size_t)(k0 + brow)     * LDB + bcol);
        const float4 b1 = *(const float4*)(Bb + (size_t)(k0 + brow + 8) * LDB + bcol);
        __syncthreads();
        As[acol + 0][arow]      = a0.x; As[acol + 1][arow]      = a0.y;
        As[acol + 2][arow]      = a0.z; As[acol + 3][arow]      = a0.w;
        As[acol + 0][arow + 64] = a1.x; As[acol + 1][arow + 64] = a1.y;
        As[acol + 2][arow + 64] = a1.z; As[acol + 3][arow + 64] = a1.w;
        *(float4*)&Bs[brow][bcol]     = b0;
        *(float4*)&Bs[brow + 8][bcol] = b1;
        __syncthreads();
        #pragma unroll
        for (int kk = 0; kk < 16; kk++) {
            float a[8], b[8];
            *(float4*)(a)     = *(const float4*)&As[kk][ty * 8];
            *(float4*)(a + 4) = *(const float4*)&As[kk][ty * 8 + 4];
            *(float4*)(b)     = *(const float4*)&Bs[kk][tx * 8];
            *(float4*)(b + 4) = *(const float4*)&Bs[kk][tx * 8 + 4];
            #pragma unroll
            for (int i = 0; i < 8; i++)
                #pragma unroll
                for (int j = 0; j < 8; j++)
                    acc[i][j] = fmaf(a[i], b[j], acc[i][j]);
        }
    }

    if (MODE == 0) {
        // scatter to head-major q/k/v: dst[((b*H+h)*N + n)*DH + d]
        #pragma unroll
        for (int i = 0; i < 8; i++) {
            const int row = by * 128 + ty * 8 + i;       // token
            const int bb  = row >> 12;                   // /4096
            const int nn  = row & 4095;
            #pragma unroll
            for (int j = 0; j < 8; j++) {
                const int col  = bx * 128 + tx * 8 + j;  // 0..1535
                const int part = col >> 9;
                const int rem  = col & 511;
                const int h    = rem >> 6;
                const int d    = rem & 63;
                float* dst = (part == 0) ? g_q : ((part == 1) ? g_k : g_v);
                dst[(((size_t)bb * HEADS + h) * NSEQ + nn) * DH + d] = acc[i][j];
            }
        }
    } else {
        #pragma unroll
        for (int i = 0; i < 8; i++) {
            const int row = by * 128 + ty * 8 + i;
            float* cp = C + (size_t)row * DIM + bx * 128 + tx * 8;
            *(float4*)(cp)     = make_float4(acc[i][0], acc[i][1], acc[i][2], acc[i][3]);
            *(float4*)(cp + 4) = make_float4(acc[i][4], acc[i][5], acc[i][6], acc[i][7]);
        }
    }
}

// ---------------- 3) causal flash attention, Br=Bc=64, fp32 ------------------
// grid: (64 q-tiles, 16 bh). 256 threads = 16x16; thread owns 4 rows x 4 cols.
// smem: Qs 64x64 (unpadded), KPs 64x65 (K tile, later reused for P), Vs 64x64.
// Total 48896 B static -> no opt-in attribute needed.
__global__ void __launch_bounds__(256, 2) attn_kernel() {
    __shared__ float Qs [64 * 64];
    __shared__ float KPs[64 * 65];
    __shared__ float Vs [64 * 64];

    const int qt = (gridDim.x - 1) - blockIdx.x;   // big tiles first
    const int bh = blockIdx.y;
    const int tid = threadIdx.x;
    const int tx = tid & 15, ty = tid >> 4;

    const float* Qg  = g_q + ((size_t)bh * NSEQ + qt * 64) * DH;
    const float* Kg0 = g_k + (size_t)bh * NSEQ * DH;
    const float* Vg0 = g_v + (size_t)bh * NSEQ * DH;

    // load Q tile, pre-scaled by dh^-0.5 = 0.125 (exact power of 2)
    #pragma unroll
    for (int p = 0; p < 4; p++) {
        const int row = (tid >> 4) + p * 16;
        const int col = (tid & 15) * 4;
        const float4 q4 = *(const float4*)(Qg + row * 64 + col);
        Qs[row * 64 + col + 0] = q4.x * 0.125f;
        Qs[row * 64 + col + 1] = q4.y * 0.125f;
        Qs[row * 64 + col + 2] = q4.z * 0.125f;
        Qs[row * 64 + col + 3] = q4.w * 0.125f;
    }

    float o[4][4];
    float m[4], l[4];
    #pragma unroll
    for (int i = 0; i < 4; i++) {
        m[i] = -3.0e38f; l[i] = 0.f;
        #pragma unroll
        for (int j = 0; j < 4; j++) o[i][j] = 0.f;
    }

    for (int kt = 0; kt <= qt; kt++) {
        const float* Kg = Kg0 + (size_t)kt * 64 * 64;
        const float* Vg = Vg0 + (size_t)kt * 64 * 64;
        __syncthreads();   // prior iteration done reading KPs/Vs
        #pragma unroll
        for (int p = 0; p < 4; p++) {
            const int row = (tid >> 4) + p * 16;
            const int col = (tid & 15) * 4;
            const float4 k4 = *(const float4*)(Kg + row * 64 + col);
            KPs[row * 65 + col + 0] = k4.x;
            KPs[row * 65 + col + 1] = k4.y;
            KPs[row * 65 + col + 2] = k4.z;
            KPs[row * 65 + col + 3] = k4.w;
            *(float4*)&Vs[row * 64 + col] = *(const float4*)(Vg + row * 64 + col);
        }
        __syncthreads();

        // S = Q @ K^T  (Q pre-scaled)
        float s[4][4];
        #pragma unroll
        for (int i = 0; i < 4; i++)
            #pragma unroll
            for (int j = 0; j < 4; j++) s[i][j] = 0.f;
        #pragma unroll 8
        for (int k = 0; k < 64; k++) {
            float qr[4], kc[4];
            #pragma unroll
            for (int i = 0; i < 4; i++) qr[i] = Qs[(ty * 4 + i) * 64 + k];
            #pragma unroll
            for (int j = 0; j < 4; j++) kc[j] = KPs[(tx * 4 + j) * 65 + k];
            #pragma unroll
            for (int i = 0; i < 4; i++)
                #pragma unroll
                for (int j = 0; j < 4; j++)
                    s[i][j] = fmaf(qr[i], kc[j], s[i][j]);
        }
        if (kt == qt) {
            #pragma unroll
            for (int i = 0; i < 4; i++)
                #pragma unroll
                for (int j = 0; j < 4; j++)
                    if (tx * 4 + j > ty * 4 + i) s[i][j] = -3.0e38f;
        }

        // online softmax (row groups live in 16-lane shuffle groups)
        float mnew[4], corr[4];
        #pragma unroll
        for (int i = 0; i < 4; i++) {
            float rm = fmaxf(fmaxf(s[i][0], s[i][1]), fmaxf(s[i][2], s[i][3]));
            #pragma unroll
            for (int off = 1; off < 16; off <<= 1)
                rm = fmaxf(rm, __shfl_xor_sync(0xffffffffu, rm, off));
            mnew[i] = fmaxf(m[i], rm);
            corr[i] = __expf(m[i] - mnew[i]);
        }
        #pragma unroll
        for (int i = 0; i < 4; i++) {
            float rs = 0.f;
            #pragma unroll
            for (int j = 0; j < 4; j++) {
                const float p = __expf(s[i][j] - mnew[i]);
                s[i][j] = p;
                rs += p;
            }
            #pragma unroll
            for (int off = 1; off < 16; off <<= 1)
                rs += __shfl_xor_sync(0xffffffffu, rs, off);
            l[i] = l[i] * corr[i] + rs;
            m[i] = mnew[i];
            #pragma unroll
            for (int j = 0; j < 4; j++) o[i][j] *= corr[i];
        }

        __syncthreads();   // everyone done reading K from KPs
        #pragma unroll
        for (int i = 0; i < 4; i++)
            #pragma unroll
            for (int j = 0; j < 4; j++)
                KPs[(ty * 4 + i) * 65 + tx * 4 + j] = s[i][j];   // stage P
        __syncthreads();

        // O += P @ V
        #pragma unroll 8
        for (int k = 0; k < 64; k++) {
            float pr[4];
            #pragma unroll
            for (int i = 0; i < 4; i++) pr[i] = KPs[(ty * 4 + i) * 65 + k];
            const float4 vv = *(const float4*)&Vs[k * 64 + tx * 4];
            #pragma unroll
            for (int i = 0; i < 4; i++) {
                o[i][0] = fmaf(pr[i], vv.x, o[i][0]);
                o[i][1] = fmaf(pr[i], vv.y, o[i][1]);
                o[i][2] = fmaf(pr[i], vv.z, o[i][2]);
                o[i][3] = fmaf(pr[i], vv.w, o[i][3]);
            }
        }
    }

    // epilogue: normalize (denom + 1e-10 per reference) and write [token, h*64+d]
    const int b = bh >> 3, h = bh & 7;
    #pragma unroll
    for (int i = 0; i < 4; i++) {
        const int r   = qt * 64 + ty * 4 + i;
        const int tok = b * NSEQ + r;
        const float inv = 1.0f / (l[i] + 1e-10f);
        float* dst = g_ao + (size_t)tok * AO_N + h * 64 + tx * 4;
        dst[0] = o[i][0] * inv;
        dst[1] = o[i][1] * inv;
        dst[2] = o[i][2] * inv;
        dst[3] = o[i][3] * inv;
    }
}

// ---------------- launch -----------------------------------------------------
extern "C" void kernel_launch(void* const* d_in, const int* in_sizes, int n_in,
                              void* d_out, int out_size) {
    const float* x     = (const float*)d_in[0];
    const float* gamma = (const float*)d_in[1];
    const float* beta  = (const float*)d_in[2];
    const float* wqkv  = (const float*)d_in[3];
    const float* wout  = (const float*)d_in[4];
    float* out = (float*)d_out;

    ln_kernel<<<TOKENS, 256>>>(x, gamma, beta);
    gemm128<0><<<dim3(QKV_N / 128, TOKENS / 128), 256>>>(wqkv, nullptr);
    attn_kernel<<<dim3(NSEQ / 64, BATCH * HEADS), 256>>>();
    gemm128<1><<<dim3(DIM / 128, TOKENS / 128), 256>>>(wout, out);
}

// round 3
// speedup vs baseline: 2.0161x; 2.0161x over previous
#include <cuda_runtime.h>
#include <cuda_bf16.h>
#include <stdint.h>

#define DIM     1024
#define HEADS   8
#define DH      64
#define NSEQ    4096
#define BATCH   2
#define TOKENS  (BATCH*NSEQ)     // 8192
#define QKV_N   (3*HEADS*DH)     // 1536
#define AO_N    (HEADS*DH)       // 512
#define BH_N    (BATCH*HEADS)    // 16

// ===================== scratch globals =======================================
__device__ __align__(16) __nv_bfloat16 g_xn_hi[TOKENS * DIM];
__device__ __align__(16) __nv_bfloat16 g_xn_lo[TOKENS * DIM];
__device__ __align__(16) __nv_bfloat16 g_wq_hi[QKV_N * DIM];   // [1536,1024] K-major
__device__ __align__(16) __nv_bfloat16 g_wq_lo[QKV_N * DIM];
__device__ __align__(16) __nv_bfloat16 g_wo_hi[DIM * AO_N];    // [1024,512]  K-major
__device__ __align__(16) __nv_bfloat16 g_wo_lo[DIM * AO_N];
__device__ __align__(16) __nv_bfloat16 g_qh[BH_N * NSEQ * DH]; // head-major, pre-scaled
__device__ __align__(16) __nv_bfloat16 g_ql[BH_N * NSEQ * DH];
__device__ __align__(16) __nv_bfloat16 g_kh[BH_N * NSEQ * DH];
__device__ __align__(16) __nv_bfloat16 g_kl[BH_N * NSEQ * DH];
__device__ __align__(16) __nv_bfloat16 g_vh[BH_N * NSEQ * DH];
__device__ __align__(16) __nv_bfloat16 g_vl[BH_N * NSEQ * DH];
__device__ __align__(16) __nv_bfloat16 g_ao_hi[TOKENS * AO_N];
__device__ __align__(16) __nv_bfloat16 g_ao_lo[TOKENS * AO_N];

// ===================== warp-MMA helpers (portable PTX, sm_80+) ===============
__device__ __forceinline__ uint32_t smem_u32(const void* p) {
    uint32_t a;
    asm("{ .reg .u64 t; cvta.to.shared.u64 t, %1; cvt.u32.u64 %0, t; }"
        : "=r"(a) : "l"(p));
    return a;
}

__device__ __forceinline__ void ldsm4(uint32_t (&r)[4], uint32_t a) {
    asm volatile("ldmatrix.sync.aligned.m8n8.x4.shared.b16 {%0,%1,%2,%3}, [%4];"
        : "=r"(r[0]), "=r"(r[1]), "=r"(r[2]), "=r"(r[3]) : "r"(a));
}
__device__ __forceinline__ void ldsm4t(uint32_t (&r)[4], uint32_t a) {
    asm volatile("ldmatrix.sync.aligned.m8n8.x4.trans.shared.b16 {%0,%1,%2,%3}, [%4];"
        : "=r"(r[0]), "=r"(r[1]), "=r"(r[2]), "=r"(r[3]) : "r"(a));
}
__device__ __forceinline__ void mma16816(float (&d)[4], const uint32_t (&a)[4],
                                         uint32_t b0, uint32_t b1) {
    asm volatile(
        "mma.sync.aligned.m16n8k16.row.col.f32.bf16.bf16.f32 "
        "{%0,%1,%2,%3}, {%4,%5,%6,%7}, {%8,%9}, {%0,%1,%2,%3};"
        : "+f"(d[0]), "+f"(d[1]), "+f"(d[2]), "+f"(d[3])
        : "r"(a[0]), "r"(a[1]), "r"(a[2]), "r"(a[3]), "r"(b0), "r"(b1));
}
// pack two f32 into bf16x2 (x0 -> low half), plus residual pack
__device__ __forceinline__ void pack_split(float x0, float x1,
                                           uint32_t& ph, uint32_t& pl) {
    uint32_t hp;
    asm("cvt.rn.bf16x2.f32 %0, %1, %2;" : "=r"(hp) : "f"(x1), "f"(x0));
    __nv_bfloat162 hv = *reinterpret_cast<__nv_bfloat162*>(&hp);
    float r0 = x0 - __bfloat162float(hv.x);
    float r1 = x1 - __bfloat162float(hv.y);
    asm("cvt.rn.bf16x2.f32 %0, %1, %2;" : "=r"(pl) : "f"(r1), "f"(r0));
    ph = hp;
}
// 128-byte-row XOR swizzle (16B chunks), cb must be a multiple of 16
__device__ __forceinline__ uint32_t sw128(int r, int cb) {
    return (uint32_t)(r * 128 + ((((cb >> 4) ^ (r & 7))) << 4));
}

// ===================== 1) LayerNorm -> bf16 hi/lo ============================
__global__ void ln_kernel(const float* __restrict__ x,
                          const float* __restrict__ gamma,
                          const float* __restrict__ beta) {
    const int t   = blockIdx.x;
    const int tid = threadIdx.x;
    const float4 v = *(const float4*)(x + (size_t)t * DIM + tid * 4);

    float s  = v.x + v.y + v.z + v.w;
    float s2 = v.x*v.x + v.y*v.y + v.z*v.z + v.w*v.w;
    #pragma unroll
    for (int o = 16; o > 0; o >>= 1) {
        s  += __shfl_down_sync(0xffffffffu, s,  o);
        s2 += __shfl_down_sync(0xffffffffu, s2, o);
    }
    __shared__ float ws[8], ws2[8];
    __shared__ float s_mu, s_rstd;
    const int wid = tid >> 5, lane = tid & 31;
    if (lane == 0) { ws[wid] = s; ws2[wid] = s2; }
    __syncthreads();
    if (tid == 0) {
        float S = 0.f, S2 = 0.f;
        #pragma unroll
        for (int i = 0; i < 8; i++) { S += ws[i]; S2 += ws2[i]; }
        float mu  = S * (1.0f / DIM);
        float var = S2 * (1.0f / DIM) - mu * mu;
        s_mu = mu;
        s_rstd = rsqrtf(var + 1e-5f);
    }
    __syncthreads();
    const float mu = s_mu, rstd = s_rstd;
    const float4 g = *(const float4*)(gamma + tid * 4);
    const float4 b = *(const float4*)(beta  + tid * 4);
    float y[4];
    y[0] = (v.x - mu) * rstd * g.x + b.x;
    y[1] = (v.y - mu) * rstd * g.y + b.y;
    y[2] = (v.z - mu) * rstd * g.z + b.z;
    y[3] = (v.w - mu) * rstd * g.w + b.w;

    const size_t o = (size_t)t * DIM + tid * 4;
    uint32_t h0, l0, h1, l1;
    pack_split(y[0], y[1], h0, l0);
    pack_split(y[2], y[3], h1, l1);
    *(uint32_t*)(g_xn_hi + o)     = h0;
    *(uint32_t*)(g_xn_hi + o + 2) = h1;
    *(uint32_t*)(g_xn_lo + o)     = l0;
    *(uint32_t*)(g_xn_lo + o + 2) = l1;
}

// ===================== 2) weight transpose + bf16 split ======================
template<int W>
__global__ void conv_w(const float* __restrict__ src) {
    constexpr int Kd = (W == 0) ? DIM : AO_N;
    constexpr int Nd = (W == 0) ? QKV_N : DIM;
    __nv_bfloat16* hi = (W == 0) ? g_wq_hi : g_wo_hi;
    __nv_bfloat16* lo = (W == 0) ? g_wq_lo : g_wo_lo;
    const int idx = blockIdx.x * 256 + threadIdx.x;
    if (idx >= Kd * Nd) return;
    const int k = idx / Nd, n = idx % Nd;
    const float v = src[idx];
    const __nv_bfloat16 h = __float2bfloat16(v);
    hi[(size_t)n * Kd + k] = h;
    lo[(size_t)n * Kd + k] = __float2bfloat16(v - __bfloat162float(h));
}

// ===================== 3) bf16x3 mma.sync GEMM, 128x128 tile, Kc=32 ==========
// MODE 0: A=g_xn [8192,1024], B=g_wq [1536,1024] -> scatter q/k/v bf16 hi/lo
// MODE 1: A=g_ao [8192,512],  B=g_wo [1024,512]  -> C fp32 [8192,1024]
template<int MODE>
__global__ void __launch_bounds__(256) gemm_mma(float* __restrict__ Cout) {
    constexpr int K = (MODE == 0) ? DIM : AO_N;
    __shared__ __align__(16) char sAh[128 * 80];
    __shared__ __align__(16) char sAl[128 * 80];
    __shared__ __align__(16) char sBh[128 * 80];
    __shared__ __align__(16) char sBl[128 * 80];

    const int tid = threadIdx.x, lane = tid & 31, warp = tid >> 5;
    const int g = lane >> 2, tig = lane & 3;
    const int wm = (warp >> 1) * 32, wn = (warp & 1) * 64;
    const int m0 = blockIdx.y * 128, n0 = blockIdx.x * 128;

    const __nv_bfloat16* __restrict__ Ah = (MODE == 0) ? g_xn_hi : g_ao_hi;
    const __nv_bfloat16* __restrict__ Al = (MODE == 0) ? g_xn_lo : g_ao_lo;
    const __nv_bfloat16* __restrict__ Bh = (MODE == 0) ? g_wq_hi : g_wo_hi;
    const __nv_bfloat16* __restrict__ Bl = (MODE == 0) ? g_wq_lo : g_wo_lo;

    const uint32_t uAh = smem_u32(sAh), uAl = smem_u32(sAl);
    const uint32_t uBh = smem_u32(sBh), uBl = smem_u32(sBl);

    float c[2][8][4] = {};
    const int lr = tid >> 2, lc = tid & 3;   // loader: row, 16B-chunk

    for (int k0 = 0; k0 < K; k0 += 32) {
        __syncthreads();
        #pragma unroll
        for (int it = 0; it < 2; it++) {
            const int r = lr + it * 64;
            const size_t ga = (size_t)(m0 + r) * K + k0 + lc * 8;
            const size_t gb = (size_t)(n0 + r) * K + k0 + lc * 8;
            *(uint4*)(sAh + r * 80 + lc * 16) = *(const uint4*)(Ah + ga);
            *(uint4*)(sAl + r * 80 + lc * 16) = *(const uint4*)(Al + ga);
            *(uint4*)(sBh + r * 80 + lc * 16) = *(const uint4*)(Bh + gb);
            *(uint4*)(sBl + r * 80 + lc * 16) = *(const uint4*)(Bl + gb);
        }
        __syncthreads();
        #pragma unroll
        for (int hh = 0; hh < 2; hh++) {
            const int acb = hh * 32 + (lane >> 4) * 16;
            uint32_t ah[2][4], al[2][4];
            #pragma unroll
            for (int i = 0; i < 2; i++) {
                const uint32_t ro = (uint32_t)((wm + i * 16 + (lane & 15)) * 80 + acb);
                ldsm4(ah[i], uAh + ro);
                ldsm4(al[i], uAl + ro);
            }
            #pragma unroll
            for (int nb = 0; nb < 4; nb++) {
                uint32_t bhh[4], bll[4];
                const uint32_t ro = (uint32_t)((wn + nb * 16 + (lane & 7)
                                   + ((lane >> 3) & 1) * 8) * 80 + acb);
                ldsm4(bhh, uBh + ro);
                ldsm4(bll, uBl + ro);
                #pragma unroll
                for (int i = 0; i < 2; i++) {
                    mma16816(c[i][nb*2+0], ah[i], bhh[0], bhh[2]);
                    mma16816(c[i][nb*2+1], ah[i], bhh[1], bhh[3]);
                    mma16816(c[i][nb*2+0], ah[i], bll[0], bll[2]);
                    mma16816(c[i][nb*2+1], ah[i], bll[1], bll[3]);
                    mma16816(c[i][nb*2+0], al[i], bhh[0], bhh[2]);
                    mma16816(c[i][nb*2+1], al[i], bhh[1], bhh[3]);
                }
            }
        }
    }

    if (MODE == 0) {
        #pragma unroll
        for (int i = 0; i < 2; i++) {
            const int r0g = m0 + wm + i * 16 + g;
            #pragma unroll
            for (int j = 0; j < 8; j++) {
                const int col  = n0 + wn + j * 8 + tig * 2;
                const int part = col >> 9;
                const int hd   = (col >> 6) & 7;
                const int d    = col & 63;
                __nv_bfloat16* dh_ = (part == 0) ? g_qh : ((part == 1) ? g_kh : g_vh);
                __nv_bfloat16* dl_ = (part == 0) ? g_ql : ((part == 1) ? g_kl : g_vl);
                const float sc = (part == 0) ? 0.125f : 1.0f;
                #pragma unroll
                for (int rr = 0; rr < 2; rr++) {
                    const int row = r0g + rr * 8;
                    const int bb = row >> 12, seq = row & 4095;
                    const size_t off = (((size_t)(bb * HEADS + hd)) * NSEQ + seq) * DH + d;
                    uint32_t ph, pl;
                    pack_split(c[i][j][rr*2+0] * sc, c[i][j][rr*2+1] * sc, ph, pl);
                    *(uint32_t*)(dh_ + off) = ph;
                    *(uint32_t*)(dl_ + off) = pl;
                }
            }
        }
    } else {
        #pragma unroll
        for (int i = 0; i < 2; i++) {
            const int r0g = m0 + wm + i * 16 + g;
            #pragma unroll
            for (int j = 0; j < 8; j++) {
                const int col = n0 + wn + j * 8 + tig * 2;
                #pragma unroll
                for (int rr = 0; rr < 2; rr++) {
                    const int row = r0g + rr * 8;
                    *(float2*)(Cout + (size_t)row * DIM + col) =
                        make_float2(c[i][j][rr*2+0], c[i][j][rr*2+1]);
                }
            }
        }
    }
}

// ===================== 4) causal flash attention, mma.sync bf16x3 ============
// Br=128 (8 warps x m16), Bc=64. S-frag -> P-frag repack (FA2 style).
__global__ void __launch_bounds__(256) attn_kernel() {
    __shared__ __align__(16) char sm[32768];
    // layout: KH @0, KL @8192, VH @16384, VL @24576 (each 64x64 bf16 swizzled)
    // Q staging (before loop): QH @0, QL @16384 (each 128x64 bf16 swizzled)
    const uint32_t sb = smem_u32(sm);
    const int qt = (int)gridDim.x - 1 - (int)blockIdx.x;  // big tiles first
    const int bh = blockIdx.y, b = bh >> 3, h = bh & 7;
    const int tid = threadIdx.x, lane = tid & 31, warp = tid >> 5;
    const int g = lane >> 2, tig = lane & 3;
    const int wm = warp * 16;

    // ---- stage Q and load fragments ----
    const size_t qbase = ((size_t)bh * NSEQ + qt * 128) * DH;
    for (int i = tid; i < 1024; i += 256) {     // 128 rows x 8 chunks
        const int r = i >> 3, cch = i & 7;
        const uint32_t d = sw128(r, cch * 16);
        const size_t src = qbase + (size_t)r * DH + cch * 8;
        *(uint4*)(sm + d)         = *(const uint4*)(g_qh + src);
        *(uint4*)(sm + 16384 + d) = *(const uint4*)(g_ql + src);
    }
    __syncthreads();
    uint32_t qh[4][4], ql[4][4];
    #pragma unroll
    for (int kk = 0; kk < 4; kk++) {
        const int r  = wm + (lane & 15);
        const int cb = kk * 32 + (lane >> 4) * 16;
        const uint32_t off = sw128(r, cb);
        ldsm4(qh[kk], sb + off);
        ldsm4(ql[kk], sb + 16384 + off);
    }
    __syncthreads();

    float o[8][4] = {};
    float m0v = -1e30f, m1v = -1e30f, l0 = 0.f, l1 = 0.f;
    const int ktmax = 2 * qt + 1;
    const size_t kvbase = (size_t)bh * NSEQ * DH;

    for (int kt = 0; kt <= ktmax; kt++) {
        for (int i = tid; i < 512; i += 256) {  // 64 rows x 8 chunks, x4 arrays
            const int r = i >> 3, cch = i & 7;
            const uint32_t d = sw128(r, cch * 16);
            const size_t src = kvbase + (size_t)(kt * 64 + r) * DH + cch * 8;
            *(uint4*)(sm + d)         = *(const uint4*)(g_kh + src);
            *(uint4*)(sm + 8192  + d) = *(const uint4*)(g_kl + src);
            *(uint4*)(sm + 16384 + d) = *(const uint4*)(g_vh + src);
            *(uint4*)(sm + 24576 + d) = *(const uint4*)(g_vl + src);
        }
        __syncthreads();

        // ---- S = Q K^T (3-term bf16) ----
        float s[8][4] = {};
        #pragma unroll
        for (int kk = 0; kk < 4; kk++) {
            const int cb = kk * 32 + (lane >> 4) * 16;
            #pragma unroll
            for (int nb = 0; nb < 4; nb++) {
                const int r = nb * 16 + (lane & 7) + ((lane >> 3) & 1) * 8;
                const uint32_t off = sw128(r, cb);
                uint32_t kbh[4], kbl[4];
                ldsm4(kbh, sb + off);
                ldsm4(kbl, sb + 8192 + off);
                mma16816(s[nb*2+0], qh[kk], kbh[0], kbh[2]);
                mma16816(s[nb*2+1], qh[kk], kbh[1], kbh[3]);
                mma16816(s[nb*2+0], qh[kk], kbl[0], kbl[2]);
                mma16816(s[nb*2+1], qh[kk], kbl[1], kbl[3]);
                mma16816(s[nb*2+0], ql[kk], kbh[0], kbh[2]);
                mma16816(s[nb*2+1], ql[kk], kbh[1], kbh[3]);
            }
        }
        // ---- causal mask (only diagonal tiles) ----
        if (kt >= 2 * qt) {
            const int row0 = qt * 128 + wm + g;
            #pragma unroll
            for (int j = 0; j < 8; j++) {
                const int col = kt * 64 + j * 8 + tig * 2;
                if (col     > row0)     s[j][0] = -1e30f;
                if (col + 1 > row0)     s[j][1] = -1e30f;
                if (col     > row0 + 8) s[j][2] = -1e30f;
                if (col + 1 > row0 + 8) s[j][3] = -1e30f;
            }
        }
        // ---- online softmax (rows g, g+8; reduce across quad lanes) ----
        float mx0 = -1e30f, mx1 = -1e30f;
        #pragma unroll
        for (int j = 0; j < 8; j++) {
            mx0 = fmaxf(mx0, fmaxf(s[j][0], s[j][1]));
            mx1 = fmaxf(mx1, fmaxf(s[j][2], s[j][3]));
        }
        mx0 = fmaxf(mx0, __shfl_xor_sync(0xffffffffu, mx0, 1));
        mx0 = fmaxf(mx0, __shfl_xor_sync(0xffffffffu, mx0, 2));
        mx1 = fmaxf(mx1, __shfl_xor_sync(0xffffffffu, mx1, 1));
        mx1 = fmaxf(mx1, __shfl_xor_sync(0xffffffffu, mx1, 2));
        const float mn0 = fmaxf(m0v, mx0), mn1 = fmaxf(m1v, mx1);
        const float cor0 = __expf(m0v - mn0), cor1 = __expf(m1v - mn1);
        m0v = mn0; m1v = mn1;
        float ls0 = 0.f, ls1 = 0.f;
        #pragma unroll
        for (int j = 0; j < 8; j++) {
            s[j][0] = __expf(s[j][0] - mn0);
            s[j][1] = __expf(s[j][1] - mn0);
            s[j][2] = __expf(s[j][2] - mn1);
            s[j][3] = __expf(s[j][3] - mn1);
            ls0 += s[j][0] + s[j][1];
            ls1 += s[j][2] + s[j][3];
        }
        ls0 += __shfl_xor_sync(0xffffffffu, ls0, 1);
        ls0 += __shfl_xor_sync(0xffffffffu, ls0, 2);
        ls1 += __shfl_xor_sync(0xffffffffu, ls1, 1);
        ls1 += __shfl_xor_sync(0xffffffffu, ls1, 2);
        l0 = l0 * cor0 + ls0;
        l1 = l1 * cor1 + ls1;
        #pragma unroll
        for (int j = 0; j < 8; j++) {
            o[j][0] *= cor0; o[j][1] *= cor0;
            o[j][2] *= cor1; o[j][3] *= cor1;
        }
        // ---- O += P V (3-term bf16, P repacked from S frags) ----
        #pragma unroll
        for (int kk = 0; kk < 4; kk++) {
            uint32_t pah[4], pal[4];
            pack_split(s[2*kk  ][0], s[2*kk  ][1], pah[0], pal[0]);
            pack_split(s[2*kk  ][2], s[2*kk  ][3], pah[1], pal[1]);
            pack_split(s[2*kk+1][0], s[2*kk+1][1], pah[2], pal[2]);
            pack_split(s[2*kk+1][2], s[2*kk+1][3], pah[3], pal[3]);
            #pragma unroll
            for (int nb = 0; nb < 4; nb++) {
                const int r  = kk * 16 + (lane & 7) + ((lane >> 4) << 3);
                const int cb = nb * 32 + ((lane >> 3) & 1) * 16;
                const uint32_t off = sw128(r, cb);
                uint32_t vbh[4], vbl[4];
                ldsm4t(vbh, sb + 16384 + off);
                ldsm4t(vbl, sb + 24576 + off);
                mma16816(o[nb*2+0], pah, vbh[0], vbh[2]);
                mma16816(o[nb*2+1], pah, vbh[1], vbh[3]);
                mma16816(o[nb*2+0], pah, vbl[0], vbl[2]);
                mma16816(o[nb*2+1], pah, vbl[1], vbl[3]);
                mma16816(o[nb*2+0], pal, vbh[0], vbh[2]);
                mma16816(o[nb*2+1], pal, vbh[1], vbh[3]);
            }
        }
        __syncthreads();
    }

    // ---- epilogue: normalize, split bf16 hi/lo for OUT GEMM ----
    const float inv0 = 1.0f / (l0 + 1e-10f);
    const float inv1 = 1.0f / (l1 + 1e-10f);
    const int row0 = qt * 128 + wm + g;
    #pragma unroll
    for (int j = 0; j < 8; j++) {
        const int col = h * DH + j * 8 + tig * 2;
        {
            const size_t off = (size_t)(b * NSEQ + row0) * AO_N + col;
            uint32_t ph, pl;
            pack_split(o[j][0] * inv0, o[j][1] * inv0, ph, pl);
            *(uint32_t*)(g_ao_hi + off) = ph;
            *(uint32_t*)(g_ao_lo + off) = pl;
        }
        {
            const size_t off = (size_t)(b * NSEQ + row0 + 8) * AO_N + col;
            uint32_t ph, pl;
            pack_split(o[j][2] * inv1, o[j][3] * inv1, ph, pl);
            *(uint32_t*)(g_ao_hi + off) = ph;
            *(uint32_t*)(g_ao_lo + off) = pl;
        }
    }
}

// ===================== launch ================================================
extern "C" void kernel_launch(void* const* d_in, const int* in_sizes, int n_in,
                              void* d_out, int out_size) {
    const float* x     = (const float*)d_in[0];
    const float* gamma = (const float*)d_in[1];
    const float* beta  = (const float*)d_in[2];
    const float* wqkv  = (const float*)d_in[3];
    const float* wout  = (const float*)d_in[4];
    float* out = (float*)d_out;

    ln_kernel<<<TOKENS, 256>>>(x, gamma, beta);
    conv_w<0><<<(DIM * QKV_N + 255) / 256, 256>>>(wqkv);
    conv_w<1><<<(AO_N * DIM + 255) / 256, 256>>>(wout);
    gemm_mma<0><<<dim3(QKV_N / 128, TOKENS / 128), 256>>>(nullptr);
    attn_kernel<<<dim3(NSEQ / 128, BH_N), 256>>>();
    gemm_mma<1><<<dim3(DIM / 128, TOKENS / 128), 256>>>(out);
}

// round 4
// speedup vs baseline: 2.1404x; 1.0616x over previous
#include <cuda_runtime.h>
#include <cuda_bf16.h>
#include <stdint.h>

#define DIM     1024
#define HEADS   8
#define DH      64
#define NSEQ    4096
#define BATCH   2
#define TOKENS  (BATCH*NSEQ)     // 8192
#define QKV_N   (3*HEADS*DH)     // 1536
#define AO_N    (HEADS*DH)       // 512
#define BH_N    (BATCH*HEADS)    // 16

// ===================== scratch globals =======================================
__device__ __align__(16) __nv_bfloat16 g_xn_hi[TOKENS * DIM];
__device__ __align__(16) __nv_bfloat16 g_xn_lo[TOKENS * DIM];
__device__ __align__(16) __nv_bfloat16 g_wq_hi[QKV_N * DIM];   // [1536,1024] K-major
__device__ __align__(16) __nv_bfloat16 g_wq_lo[QKV_N * DIM];
__device__ __align__(16) __nv_bfloat16 g_wo_hi[DIM * AO_N];    // [1024,512]  K-major
__device__ __align__(16) __nv_bfloat16 g_wo_lo[DIM * AO_N];
__device__ __align__(16) __nv_bfloat16 g_qh[BH_N * NSEQ * DH]; // head-major, pre-scaled
__device__ __align__(16) __nv_bfloat16 g_ql[BH_N * NSEQ * DH];
__device__ __align__(16) __nv_bfloat16 g_kh[BH_N * NSEQ * DH];
__device__ __align__(16) __nv_bfloat16 g_kl[BH_N * NSEQ * DH];
__device__ __align__(16) __nv_bfloat16 g_vh[BH_N * NSEQ * DH];
__device__ __align__(16) __nv_bfloat16 g_vl[BH_N * NSEQ * DH];
__device__ __align__(16) __nv_bfloat16 g_ao_hi[TOKENS * AO_N];
__device__ __align__(16) __nv_bfloat16 g_ao_lo[TOKENS * AO_N];

// ===================== PTX helpers (portable, sm_80+) ========================
__device__ __forceinline__ uint32_t smem_u32(const void* p) {
    uint32_t a;
    asm("{ .reg .u64 t; cvta.to.shared.u64 t, %1; cvt.u32.u64 %0, t; }"
        : "=r"(a) : "l"(p));
    return a;
}
__device__ __forceinline__ void cp16(uint32_t dst, const void* src) {
    asm volatile("cp.async.cg.shared.global [%0], [%1], 16;"
                 :: "r"(dst), "l"(src));
}
#define CP_COMMIT() asm volatile("cp.async.commit_group;" ::: "memory")
#define CP_WAIT1()  asm volatile("cp.async.wait_group 1;"  ::: "memory")

__device__ __forceinline__ void ldsm4(uint32_t (&r)[4], uint32_t a) {
    asm volatile("ldmatrix.sync.aligned.m8n8.x4.shared.b16 {%0,%1,%2,%3}, [%4];"
        : "=r"(r[0]), "=r"(r[1]), "=r"(r[2]), "=r"(r[3]) : "r"(a));
}
__device__ __forceinline__ void ldsm4t(uint32_t (&r)[4], uint32_t a) {
    asm volatile("ldmatrix.sync.aligned.m8n8.x4.trans.shared.b16 {%0,%1,%2,%3}, [%4];"
        : "=r"(r[0]), "=r"(r[1]), "=r"(r[2]), "=r"(r[3]) : "r"(a));
}
__device__ __forceinline__ void mma16816(float (&d)[4], const uint32_t (&a)[4],
                                         uint32_t b0, uint32_t b1) {
    asm volatile(
        "mma.sync.aligned.m16n8k16.row.col.f32.bf16.bf16.f32 "
        "{%0,%1,%2,%3}, {%4,%5,%6,%7}, {%8,%9}, {%0,%1,%2,%3};"
        : "+f"(d[0]), "+f"(d[1]), "+f"(d[2]), "+f"(d[3])
        : "r"(a[0]), "r"(a[1]), "r"(a[2]), "r"(a[3]), "r"(b0), "r"(b1));
}
__device__ __forceinline__ void pack_split(float x0, float x1,
                                           uint32_t& ph, uint32_t& pl) {
    uint32_t hp;
    asm("cvt.rn.bf16x2.f32 %0, %1, %2;" : "=r"(hp) : "f"(x1), "f"(x0));
    __nv_bfloat162 hv = *reinterpret_cast<__nv_bfloat162*>(&hp);
    float r0 = x0 - __bfloat162float(hv.x);
    float r1 = x1 - __bfloat162float(hv.y);
    asm("cvt.rn.bf16x2.f32 %0, %1, %2;" : "=r"(pl) : "f"(r1), "f"(r0));
    ph = hp;
}
// 128-byte-row XOR swizzle (16B chunks)
__device__ __forceinline__ uint32_t sw128(int r, int cb) {
    return (uint32_t)(r * 128 + ((((cb >> 4) ^ (r & 7))) << 4));
}

// ===================== 1) LayerNorm -> bf16 hi/lo ============================
__global__ void ln_kernel(const float* __restrict__ x,
                          const float* __restrict__ gamma,
                          const float* __restrict__ beta) {
    const int t   = blockIdx.x;
    const int tid = threadIdx.x;
    const float4 v = *(const float4*)(x + (size_t)t * DIM + tid * 4);

    float s  = v.x + v.y + v.z + v.w;
    float s2 = v.x*v.x + v.y*v.y + v.z*v.z + v.w*v.w;
    #pragma unroll
    for (int o = 16; o > 0; o >>= 1) {
        s  += __shfl_down_sync(0xffffffffu, s,  o);
        s2 += __shfl_down_sync(0xffffffffu, s2, o);
    }
    __shared__ float ws[8], ws2[8];
    __shared__ float s_mu, s_rstd;
    const int wid = tid >> 5, lane = tid & 31;
    if (lane == 0) { ws[wid] = s; ws2[wid] = s2; }
    __syncthreads();
    if (tid == 0) {
        float S = 0.f, S2 = 0.f;
        #pragma unroll
        for (int i = 0; i < 8; i++) { S += ws[i]; S2 += ws2[i]; }
        float mu  = S * (1.0f / DIM);
        float var = S2 * (1.0f / DIM) - mu * mu;
        s_mu = mu;
        s_rstd = rsqrtf(var + 1e-5f);
    }
    __syncthreads();
    const float mu = s_mu, rstd = s_rstd;
    const float4 g = *(const float4*)(gamma + tid * 4);
    const float4 b = *(const float4*)(beta  + tid * 4);
    float y[4];
    y[0] = (v.x - mu) * rstd * g.x + b.x;
    y[1] = (v.y - mu) * rstd * g.y + b.y;
    y[2] = (v.z - mu) * rstd * g.z + b.z;
    y[3] = (v.w - mu) * rstd * g.w + b.w;

    const size_t o = (size_t)t * DIM + tid * 4;
    uint32_t h0, l0, h1, l1;
    pack_split(y[0], y[1], h0, l0);
    pack_split(y[2], y[3], h1, l1);
    *(uint32_t*)(g_xn_hi + o)     = h0;
    *(uint32_t*)(g_xn_hi + o + 2) = h1;
    *(uint32_t*)(g_xn_lo + o)     = l0;
    *(uint32_t*)(g_xn_lo + o + 2) = l1;
}

// ===================== 2) weight transpose + bf16 split (smem tiles) =========
template<int W>
__global__ void conv_w(const float* __restrict__ src) {
    constexpr int Kd = (W == 0) ? DIM : AO_N;
    constexpr int Nd = (W == 0) ? QKV_N : DIM;
    __nv_bfloat16* hi = (W == 0) ? g_wq_hi : g_wo_hi;
    __nv_bfloat16* lo = (W == 0) ? g_wq_lo : g_wo_lo;
    __shared__ float t[32][33];
    const int n0 = blockIdx.x * 32, k0 = blockIdx.y * 32;
    const int tx = threadIdx.x, ty = threadIdx.y;
    #pragma unroll
    for (int i = ty; i < 32; i += 8)
        t[i][tx] = src[(size_t)(k0 + i) * Nd + n0 + tx];
    __syncthreads();
    #pragma unroll
    for (int i = ty; i < 32; i += 8) {
        const float v = t[tx][i];
        const __nv_bfloat16 h = __float2bfloat16(v);
        const size_t off = (size_t)(n0 + i) * Kd + k0 + tx;
        hi[off] = h;
        lo[off] = __float2bfloat16(v - __bfloat162float(h));
    }
}

// ===================== 3) bf16x3 mma.sync GEMM, 128x128, cp.async 2-stage ====
// stage layout (40960 B): Ah@0, Al@10240, Bh@20480, Bl@30720 — 128 rows x 80B
#define GST 40960
__device__ __forceinline__ void gemm_load(uint32_t sb, int st,
    const __nv_bfloat16* __restrict__ Ah, const __nv_bfloat16* __restrict__ Al,
    const __nv_bfloat16* __restrict__ Bh, const __nv_bfloat16* __restrict__ Bl,
    int m0, int n0, int K, int k0, int tid)
{
    const int r  = tid >> 1;
    const int c0 = (tid & 1) * 2;
    const uint32_t base = sb + st * GST;
    #pragma unroll
    for (int it = 0; it < 2; it++) {
        const int ch = c0 + it;
        const uint32_t d = base + r * 80 + ch * 16;
        const size_t ga = (size_t)(m0 + r) * K + k0 + ch * 8;
        const size_t gb = (size_t)(n0 + r) * K + k0 + ch * 8;
        cp16(d,         Ah + ga);
        cp16(d + 10240, Al + ga);
        cp16(d + 20480, Bh + gb);
        cp16(d + 30720, Bl + gb);
    }
}

template<int MODE>
__global__ void __launch_bounds__(256) gemm_mma(float* __restrict__ Cout) {
    constexpr int K  = (MODE == 0) ? DIM : AO_N;
    constexpr int NC = K / 32;
    extern __shared__ char dsm[];
    const uint32_t sb = smem_u32(dsm);

    const int tid = threadIdx.x, lane = tid & 31, warp = tid >> 5;
    const int g = lane >> 2, tig = lane & 3;
    const int wm = (warp >> 1) * 32, wn = (warp & 1) * 64;
    const int m0 = blockIdx.y * 128, n0 = blockIdx.x * 128;

    const __nv_bfloat16* __restrict__ Ah = (MODE == 0) ? g_xn_hi : g_ao_hi;
    const __nv_bfloat16* __restrict__ Al = (MODE == 0) ? g_xn_lo : g_ao_lo;
    const __nv_bfloat16* __restrict__ Bh = (MODE == 0) ? g_wq_hi : g_wo_hi;
    const __nv_bfloat16* __restrict__ Bl = (MODE == 0) ? g_wq_lo : g_wo_lo;

    float c[2][8][4] = {};

    gemm_load(sb, 0, Ah, Al, Bh, Bl, m0, n0, K, 0, tid);
    CP_COMMIT();

    for (int cc = 0; cc < NC; cc++) {
        __syncthreads();                      // prior compute done with buf (cc+1)&1
        if (cc + 1 < NC)
            gemm_load(sb, (cc + 1) & 1, Ah, Al, Bh, Bl, m0, n0, K, (cc + 1) * 32, tid);
        CP_COMMIT();
        CP_WAIT1();                           // group cc complete
        __syncthreads();

        const uint32_t uAh = sb + (cc & 1) * GST;
        const uint32_t uAl = uAh + 10240;
        const uint32_t uBh = uAh + 20480;
        const uint32_t uBl = uAh + 30720;

        #pragma unroll
        for (int hh = 0; hh < 2; hh++) {
            const int acb = hh * 32 + (lane >> 4) * 16;
            uint32_t ah[2][4], al[2][4];
            #pragma unroll
            for (int i = 0; i < 2; i++) {
                const uint32_t ro = (uint32_t)((wm + i * 16 + (lane & 15)) * 80 + acb);
                ldsm4(ah[i], uAh + ro);
                ldsm4(al[i], uAl + ro);
            }
            #pragma unroll
            for (int nb = 0; nb < 4; nb++) {
                uint32_t bhh[4], bll[4];
                const uint32_t ro = (uint32_t)((wn + nb * 16 + (lane & 7)
                                   + ((lane >> 3) & 1) * 8) * 80 + acb);
                ldsm4(bhh, uBh + ro);
                ldsm4(bll, uBl + ro);
                #pragma unroll
                for (int i = 0; i < 2; i++) {
                    mma16816(c[i][nb*2+0], ah[i], bhh[0], bhh[2]);
                    mma16816(c[i][nb*2+1], ah[i], bhh[1], bhh[3]);
                    mma16816(c[i][nb*2+0], ah[i], bll[0], bll[2]);
                    mma16816(c[i][nb*2+1], ah[i], bll[1], bll[3]);
                    mma16816(c[i][nb*2+0], al[i], bhh[0], bhh[2]);
                    mma16816(c[i][nb*2+1], al[i], bhh[1], bhh[3]);
                }
            }
        }
    }

    if (MODE == 0) {
        #pragma unroll
        for (int i = 0; i < 2; i++) {
            const int r0g = m0 + wm + i * 16 + g;
            #pragma unroll
            for (int j = 0; j < 8; j++) {
                const int col  = n0 + wn + j * 8 + tig * 2;
                const int part = col >> 9;
                const int hd   = (col >> 6) & 7;
                const int d    = col & 63;
                __nv_bfloat16* dh_ = (part == 0) ? g_qh : ((part == 1) ? g_kh : g_vh);
                __nv_bfloat16* dl_ = (part == 0) ? g_ql : ((part == 1) ? g_kl : g_vl);
                const float sc = (part == 0) ? 0.125f : 1.0f;
                #pragma unroll
                for (int rr = 0; rr < 2; rr++) {
                    const int row = r0g + rr * 8;
                    const int bb = row >> 12, seq = row & 4095;
                    const size_t off = (((size_t)(bb * HEADS + hd)) * NSEQ + seq) * DH + d;
                    uint32_t ph, pl;
                    pack_split(c[i][j][rr*2+0] * sc, c[i][j][rr*2+1] * sc, ph, pl);
                    *(uint32_t*)(dh_ + off) = ph;
                    *(uint32_t*)(dl_ + off) = pl;
                }
            }
        }
    } else {
        #pragma unroll
        for (int i = 0; i < 2; i++) {
            const int r0g = m0 + wm + i * 16 + g;
            #pragma unroll
            for (int j = 0; j < 8; j++) {
                const int col = n0 + wn + j * 8 + tig * 2;
                #pragma unroll
                for (int rr = 0; rr < 2; rr++) {
                    const int row = r0g + rr * 8;
                    *(float2*)(Cout + (size_t)row * DIM + col) =
                        make_float2(c[i][j][rr*2+0], c[i][j][rr*2+1]);
                }
            }
        }
    }
}

// ===================== 4) causal flash attention, cp.async 2-stage ===========
// stage (32768 B): KH@0, KL@8192, VH@16384, VL@24576 — 64 rows x 128B swizzled
// Q staged in stage-1 area during prologue. Total dynamic smem 65536.
#define AST 32768
__device__ __forceinline__ void kv_load(uint32_t sb, int st, size_t kvbase,
                                        int kt, int tid) {
    const int r  = tid >> 2;
    const int c0 = (tid & 3) * 2;
    const uint32_t base = sb + st * AST;
    #pragma unroll
    for (int it = 0; it < 2; it++) {
        const int ch = c0 + it;
        const uint32_t d = base + sw128(r, ch * 16);
        const size_t src = kvbase + (size_t)(kt * 64 + r) * DH + ch * 8;
        cp16(d,         g_kh + src);
        cp16(d + 8192,  g_kl + src);
        cp16(d + 16384, g_vh + src);
        cp16(d + 24576, g_vl + src);
    }
}

__global__ void __launch_bounds__(256) attn_kernel() {
    extern __shared__ char dsm[];
    const uint32_t sb = smem_u32(dsm);
    const int qt = (int)gridDim.x - 1 - (int)blockIdx.x;  // big tiles first
    const int bh = blockIdx.y, b = bh >> 3, h = bh & 7;
    const int tid = threadIdx.x, lane = tid & 31, warp = tid >> 5;
    const int g = lane >> 2, tig = lane & 3;
    const int wm = warp * 16;
    const size_t kvbase = (size_t)bh * NSEQ * DH;

    // prefetch kv tile 0 into stage 0 (overlaps Q staging below)
    kv_load(sb, 0, kvbase, 0, tid);
    CP_COMMIT();

    // stage Q into stage-1 area: QH @32768, QL @49152
    const size_t qbase = ((size_t)bh * NSEQ + qt * 128) * DH;
    for (int i = tid; i < 1024; i += 256) {
        const int r = i >> 3, cch = i & 7;
        const uint32_t d = sw128(r, cch * 16);
        const size_t src = qbase + (size_t)r * DH + cch * 8;
        *(uint4*)(dsm + 32768 + d) = *(const uint4*)(g_qh + src);
        *(uint4*)(dsm + 49152 + d) = *(const uint4*)(g_ql + src);
    }
    __syncthreads();
    uint32_t qh[4][4], ql[4][4];
    #pragma unroll
    for (int kk = 0; kk < 4; kk++) {
        const int r  = wm + (lane & 15);
        const int cb = kk * 32 + (lane >> 4) * 16;
        const uint32_t off = sw128(r, cb);
        ldsm4(qh[kk], sb + 32768 + off);
        ldsm4(ql[kk], sb + 49152 + off);
    }

    float o[8][4] = {};
    float m0v = -1e30f, m1v = -1e30f, l0 = 0.f, l1 = 0.f;
    const int ktmax = 2 * qt + 1;

    for (int kt = 0; kt <= ktmax; kt++) {
        __syncthreads();                     // prior compute / Q-frag reads done
        if (kt + 1 <= ktmax)
            kv_load(sb, (kt + 1) & 1, kvbase, kt + 1, tid);
        CP_COMMIT();
        CP_WAIT1();                          // kv tile kt resident
        __syncthreads();

        const uint32_t uK  = sb + (kt & 1) * AST;
        const uint32_t uKl = uK + 8192;
        const uint32_t uV  = uK + 16384;
        const uint32_t uVl = uK + 24576;

        // ---- S = Q K^T (3-term bf16) ----
        float s[8][4] = {};
        #pragma unroll
        for (int kk = 0; kk < 4; kk++) {
            const int cb = kk * 32 + (lane >> 4) * 16;
            #pragma unroll
            for (int nb = 0; nb < 4; nb++) {
                const int r = nb * 16 + (lane & 7) + ((lane >> 3) & 1) * 8;
                const uint32_t off = sw128(r, cb);
                uint32_t kbh[4], kbl[4];
                ldsm4(kbh, uK  + off);
                ldsm4(kbl, uKl + off);
                mma16816(s[nb*2+0], qh[kk], kbh[0], kbh[2]);
                mma16816(s[nb*2+1], qh[kk], kbh[1], kbh[3]);
                mma16816(s[nb*2+0], qh[kk], kbl[0], kbl[2]);
                mma16816(s[nb*2+1], qh[kk], kbl[1], kbl[3]);
                mma16816(s[nb*2+0], ql[kk], kbh[0], kbh[2]);
                mma16816(s[nb*2+1], ql[kk], kbh[1], kbh[3]);
            }
        }
        // ---- causal mask (diagonal tiles only) ----
        if (kt >= 2 * qt) {
            const int row0 = qt * 128 + wm + g;
            #pragma unroll
            for (int j = 0; j < 8; j++) {
                const int col = kt * 64 + j * 8 + tig * 2;
                if (col     > row0)     s[j][0] = -1e30f;
                if (col + 1 > row0)     s[j][1] = -1e30f;
                if (col     > row0 + 8) s[j][2] = -1e30f;
                if (col + 1 > row0 + 8) s[j][3] = -1e30f;
            }
        }
        // ---- online softmax ----
        float mx0 = -1e30f, mx1 = -1e30f;
        #pragma unroll
        for (int j = 0; j < 8; j++) {
            mx0 = fmaxf(mx0, fmaxf(s[j][0], s[j][1]));
            mx1 = fmaxf(mx1, fmaxf(s[j][2], s[j][3]));
        }
        mx0 = fmaxf(mx0, __shfl_xor_sync(0xffffffffu, mx0, 1));
        mx0 = fmaxf(mx0, __shfl_xor_sync(0xffffffffu, mx0, 2));
        mx1 = fmaxf(mx1, __shfl_xor_sync(0xffffffffu, mx1, 1));
        mx1 = fmaxf(mx1, __shfl_xor_sync(0xffffffffu, mx1, 2));
        const float mn0 = fmaxf(m0v, mx0), mn1 = fmaxf(m1v, mx1);
        const float cor0 = __expf(m0v - mn0), cor1 = __expf(m1v - mn1);
        m0v = mn0; m1v = mn1;
        float ls0 = 0.f, ls1 = 0.f;
        #pragma unroll
        for (int j = 0; j < 8; j++) {
            s[j][0] = __expf(s[j][0] - mn0);
            s[j][1] = __expf(s[j][1] - mn0);
            s[j][2] = __expf(s[j][2] - mn1);
            s[j][3] = __expf(s[j][3] - mn1);
            ls0 += s[j][0] + s[j][1];
            ls1 += s[j][2] + s[j][3];
        }
        ls0 += __shfl_xor_sync(0xffffffffu, ls0, 1);
        ls0 += __shfl_xor_sync(0xffffffffu, ls0, 2);
        ls1 += __shfl_xor_sync(0xffffffffu, ls1, 1);
        ls1 += __shfl_xor_sync(0xffffffffu, ls1, 2);
        l0 = l0 * cor0 + ls0;
        l1 = l1 * cor1 + ls1;
        #pragma unroll
        for (int j = 0; j < 8; j++) {
            o[j][0] *= cor0; o[j][1] *= cor0;
            o[j][2] *= cor1; o[j][3] *= cor1;
        }
        // ---- O += P V (3-term bf16) ----
        #pragma unroll
        for (int kk = 0; kk < 4; kk++) {
            uint32_t pah[4], pal[4];
            pack_split(s[2*kk  ][0], s[2*kk  ][1], pah[0], pal[0]);
            pack_split(s[2*kk  ][2], s[2*kk  ][3], pah[1], pal[1]);
            pack_split(s[2*kk+1][0], s[2*kk+1][1], pah[2], pal[2]);
            pack_split(s[2*kk+1][2], s[2*kk+1][3], pah[3], pal[3]);
            #pragma unroll
            for (int nb = 0; nb < 4; nb++) {
                const int r  = kk * 16 + (lane & 7) + ((lane >> 4) << 3);
                const int cb = nb * 32 + ((lane >> 3) & 1) * 16;
                const uint32_t off = sw128(r, cb);
                uint32_t vbh[4], vbl[4];
                ldsm4t(vbh, uV  + off);
                ldsm4t(vbl, uVl + off);
                mma16816(o[nb*2+0], pah, vbh[0], vbh[2]);
                mma16816(o[nb*2+1], pah, vbh[1], vbh[3]);
                mma16816(o[nb*2+0], pah, vbl[0], vbl[2]);
                mma16816(o[nb*2+1], pah, vbl[1], vbl[3]);
                mma16816(o[nb*2+0], pal, vbh[0], vbh[2]);
                mma16816(o[nb*2+1], pal, vbh[1], vbh[3]);
            }
        }
    }

    // ---- epilogue ----
    const float inv0 = 1.0f / (l0 + 1e-10f);
    const float inv1 = 1.0f / (l1 + 1e-10f);
    const int row0 = qt * 128 + wm + g;
    #pragma unroll
    for (int j = 0; j < 8; j++) {
        const int col = h * DH + j * 8 + tig * 2;
        {
            const size_t off = (size_t)(b * NSEQ + row0) * AO_N + col;
            uint32_t ph, pl;
            pack_split(o[j][0] * inv0, o[j][1] * inv0, ph, pl);
            *(uint32_t*)(g_ao_hi + off) = ph;
            *(uint32_t*)(g_ao_lo + off) = pl;
        }
        {
            const size_t off = (size_t)(b * NSEQ + row0 + 8) * AO_N + col;
            uint32_t ph, pl;
            pack_split(o[j][2] * inv1, o[j][3] * inv1, ph, pl);
            *(uint32_t*)(g_ao_hi + off) = ph;
            *(uint32_t*)(g_ao_lo + off) = pl;
        }
    }
}

// ===================== launch ================================================
extern "C" void kernel_launch(void* const* d_in, const int* in_sizes, int n_in,
                              void* d_out, int out_size) {
    const float* x     = (const float*)d_in[0];
    const float* gamma = (const float*)d_in[1];
    const float* beta  = (const float*)d_in[2];
    const float* wqkv  = (const float*)d_in[3];
    const float* wout  = (const float*)d_in[4];
    float* out = (float*)d_out;

    cudaFuncSetAttribute(gemm_mma<0>, cudaFuncAttributeMaxDynamicSharedMemorySize, 2 * GST);
    cudaFuncSetAttribute(gemm_mma<1>, cudaFuncAttributeMaxDynamicSharedMemorySize, 2 * GST);
    cudaFuncSetAttribute(attn_kernel, cudaFuncAttributeMaxDynamicSharedMemorySize, 2 * AST);

    ln_kernel<<<TOKENS, 256>>>(x, gamma, beta);
    conv_w<0><<<dim3(QKV_N / 32, DIM / 32), dim3(32, 8)>>>(wqkv);
    conv_w<1><<<dim3(DIM / 32, AO_N / 32), dim3(32, 8)>>>(wout);
    gemm_mma<0><<<dim3(QKV_N / 128, TOKENS / 128), 256, 2 * GST>>>(nullptr);
    attn_kernel<<<dim3(NSEQ / 128, BH_N), 256, 2 * AST>>>();
    gemm_mma<1><<<dim3(DIM / 128, TOKENS / 128), 256, 2 * GST>>>(out);
}

// round 5
// speedup vs baseline: 2.3039x; 1.0764x over previous
#include <cuda_runtime.h>
#include <cuda_bf16.h>
#include <stdint.h>

#define DIM     1024
#define HEADS   8
#define DH      64
#define NSEQ    4096
#define BATCH   2
#define TOKENS  (BATCH*NSEQ)     // 8192
#define QKV_N   (3*HEADS*DH)     // 1536
#define AO_N    (HEADS*DH)       // 512
#define BH_N    (BATCH*HEADS)    // 16

// ===================== scratch globals =======================================
__device__ __align__(16) __nv_bfloat16 g_xn_hi[TOKENS * DIM];
__device__ __align__(16) __nv_bfloat16 g_xn_lo[TOKENS * DIM];
__device__ __align__(16) __nv_bfloat16 g_wq_hi[QKV_N * DIM];   // [1536,1024] K-major
__device__ __align__(16) __nv_bfloat16 g_wq_lo[QKV_N * DIM];
__device__ __align__(16) __nv_bfloat16 g_wo_hi[DIM * AO_N];    // [1024,512]  K-major
__device__ __align__(16) __nv_bfloat16 g_wo_lo[DIM * AO_N];
__device__ __align__(16) __nv_bfloat16 g_qh[BH_N * NSEQ * DH]; // head-major, pre-scaled
__device__ __align__(16) __nv_bfloat16 g_ql[BH_N * NSEQ * DH];
__device__ __align__(16) __nv_bfloat16 g_kh[BH_N * NSEQ * DH];
__device__ __align__(16) __nv_bfloat16 g_kl[BH_N * NSEQ * DH];
__device__ __align__(16) __nv_bfloat16 g_vh[BH_N * NSEQ * DH];
__device__ __align__(16) __nv_bfloat16 g_vl[BH_N * NSEQ * DH];
__device__ __align__(16) __nv_bfloat16 g_ao_hi[TOKENS * AO_N];
__device__ __align__(16) __nv_bfloat16 g_ao_lo[TOKENS * AO_N];

// ===================== PTX helpers (portable, sm_80+) ========================
__device__ __forceinline__ uint32_t smem_u32(const void* p) {
    uint32_t a;
    asm("{ .reg .u64 t; cvta.to.shared.u64 t, %1; cvt.u32.u64 %0, t; }"
        : "=r"(a) : "l"(p));
    return a;
}
__device__ __forceinline__ void cp16(uint32_t dst, const void* src) {
    asm volatile("cp.async.cg.shared.global [%0], [%1], 16;"
                 :: "r"(dst), "l"(src));
}
#define CP_COMMIT() asm volatile("cp.async.commit_group;" ::: "memory")
#define CP_WAIT1()  asm volatile("cp.async.wait_group 1;"  ::: "memory")

__device__ __forceinline__ void ldsm4(uint32_t (&r)[4], uint32_t a) {
    asm volatile("ldmatrix.sync.aligned.m8n8.x4.shared.b16 {%0,%1,%2,%3}, [%4];"
        : "=r"(r[0]), "=r"(r[1]), "=r"(r[2]), "=r"(r[3]) : "r"(a));
}
__device__ __forceinline__ void ldsm4t(uint32_t (&r)[4], uint32_t a) {
    asm volatile("ldmatrix.sync.aligned.m8n8.x4.trans.shared.b16 {%0,%1,%2,%3}, [%4];"
        : "=r"(r[0]), "=r"(r[1]), "=r"(r[2]), "=r"(r[3]) : "r"(a));
}
__device__ __forceinline__ void mma16816(float (&d)[4], const uint32_t (&a)[4],
                                         uint32_t b0, uint32_t b1) {
    asm volatile(
        "mma.sync.aligned.m16n8k16.row.col.f32.bf16.bf16.f32 "
        "{%0,%1,%2,%3}, {%4,%5,%6,%7}, {%8,%9}, {%0,%1,%2,%3};"
        : "+f"(d[0]), "+f"(d[1]), "+f"(d[2]), "+f"(d[3])
        : "r"(a[0]), "r"(a[1]), "r"(a[2]), "r"(a[3]), "r"(b0), "r"(b1));
}
__device__ __forceinline__ void pack_split(float x0, float x1,
                                           uint32_t& ph, uint32_t& pl) {
    uint32_t hp;
    asm("cvt.rn.bf16x2.f32 %0, %1, %2;" : "=r"(hp) : "f"(x1), "f"(x0));
    __nv_bfloat162 hv = *reinterpret_cast<__nv_bfloat162*>(&hp);
    float r0 = x0 - __bfloat162float(hv.x);
    float r1 = x1 - __bfloat162float(hv.y);
    asm("cvt.rn.bf16x2.f32 %0, %1, %2;" : "=r"(pl) : "f"(r1), "f"(r0));
    ph = hp;
}
// 128-byte-row XOR swizzle (16B chunks)
__device__ __forceinline__ uint32_t sw128(int r, int cb) {
    return (uint32_t)(r * 128 + ((((cb >> 4) ^ (r & 7))) << 4));
}

// ===================== 1) LayerNorm -> bf16 hi/lo ============================
__global__ void ln_kernel(const float* __restrict__ x,
                          const float* __restrict__ gamma,
                          const float* __restrict__ beta) {
    const int t   = blockIdx.x;
    const int tid = threadIdx.x;
    const float4 v = *(const float4*)(x + (size_t)t * DIM + tid * 4);

    float s  = v.x + v.y + v.z + v.w;
    float s2 = v.x*v.x + v.y*v.y + v.z*v.z + v.w*v.w;
    #pragma unroll
    for (int o = 16; o > 0; o >>= 1) {
        s  += __shfl_down_sync(0xffffffffu, s,  o);
        s2 += __shfl_down_sync(0xffffffffu, s2, o);
    }
    __shared__ float ws[8], ws2[8];
    __shared__ float s_mu, s_rstd;
    const int wid = tid >> 5, lane = tid & 31;
    if (lane == 0) { ws[wid] = s; ws2[wid] = s2; }
    __syncthreads();
    if (tid == 0) {
        float S = 0.f, S2 = 0.f;
        #pragma unroll
        for (int i = 0; i < 8; i++) { S += ws[i]; S2 += ws2[i]; }
        float mu  = S * (1.0f / DIM);
        float var = S2 * (1.0f / DIM) - mu * mu;
        s_mu = mu;
        s_rstd = rsqrtf(var + 1e-5f);
    }
    __syncthreads();
    const float mu = s_mu, rstd = s_rstd;
    const float4 g = *(const float4*)(gamma + tid * 4);
    const float4 b = *(const float4*)(beta  + tid * 4);
    float y[4];
    y[0] = (v.x - mu) * rstd * g.x + b.x;
    y[1] = (v.y - mu) * rstd * g.y + b.y;
    y[2] = (v.z - mu) * rstd * g.z + b.z;
    y[3] = (v.w - mu) * rstd * g.w + b.w;

    const size_t o = (size_t)t * DIM + tid * 4;
    uint32_t h0, l0, h1, l1;
    pack_split(y[0], y[1], h0, l0);
    pack_split(y[2], y[3], h1, l1);
    *(uint32_t*)(g_xn_hi + o)     = h0;
    *(uint32_t*)(g_xn_hi + o + 2) = h1;
    *(uint32_t*)(g_xn_lo + o)     = l0;
    *(uint32_t*)(g_xn_lo + o + 2) = l1;
}

// ===================== 2) weight transpose + bf16 split (smem tiles) =========
template<int W>
__global__ void conv_w(const float* __restrict__ src) {
    constexpr int Kd = (W == 0) ? DIM : AO_N;
    constexpr int Nd = (W == 0) ? QKV_N : DIM;
    __nv_bfloat16* hi = (W == 0) ? g_wq_hi : g_wo_hi;
    __nv_bfloat16* lo = (W == 0) ? g_wq_lo : g_wo_lo;
    __shared__ float t[32][33];
    const int n0 = blockIdx.x * 32, k0 = blockIdx.y * 32;
    const int tx = threadIdx.x, ty = threadIdx.y;
    #pragma unroll
    for (int i = ty; i < 32; i += 8)
        t[i][tx] = src[(size_t)(k0 + i) * Nd + n0 + tx];
    __syncthreads();
    #pragma unroll
    for (int i = ty; i < 32; i += 8) {
        const float v = t[tx][i];
        const __nv_bfloat16 h = __float2bfloat16(v);
        const size_t off = (size_t)(n0 + i) * Kd + k0 + tx;
        hi[off] = h;
        lo[off] = __float2bfloat16(v - __bfloat162float(h));
    }
}

// ===================== 3) bf16x3 mma.sync GEMM, 128x128, cp.async 2-stage ====
// stage layout (40960 B): Ah@0, Al@10240, Bh@20480, Bl@30720 — 128 rows x 80B
#define GST 40960
__device__ __forceinline__ void gemm_load(uint32_t sb, int st,
    const __nv_bfloat16* __restrict__ Ah, const __nv_bfloat16* __restrict__ Al,
    const __nv_bfloat16* __restrict__ Bh, const __nv_bfloat16* __restrict__ Bl,
    int m0, int n0, int K, int k0, int tid)
{
    const int r  = tid >> 1;
    const int c0 = (tid & 1) * 2;
    const uint32_t base = sb + st * GST;
    #pragma unroll
    for (int it = 0; it < 2; it++) {
        const int ch = c0 + it;
        const uint32_t d = base + r * 80 + ch * 16;
        const size_t ga = (size_t)(m0 + r) * K + k0 + ch * 8;
        const size_t gb = (size_t)(n0 + r) * K + k0 + ch * 8;
        cp16(d,         Ah + ga);
        cp16(d + 10240, Al + ga);
        cp16(d + 20480, Bh + gb);
        cp16(d + 30720, Bl + gb);
    }
}

template<int MODE>
__global__ void __launch_bounds__(256, 2) gemm_mma(float* __restrict__ Cout) {
    constexpr int K  = (MODE == 0) ? DIM : AO_N;
    constexpr int NC = K / 32;
    extern __shared__ char dsm[];
    const uint32_t sb = smem_u32(dsm);

    const int tid = threadIdx.x, lane = tid & 31, warp = tid >> 5;
    const int g = lane >> 2, tig = lane & 3;
    const int wm = (warp >> 1) * 32, wn = (warp & 1) * 64;
    const int m0 = blockIdx.y * 128, n0 = blockIdx.x * 128;

    const __nv_bfloat16* __restrict__ Ah = (MODE == 0) ? g_xn_hi : g_ao_hi;
    const __nv_bfloat16* __restrict__ Al = (MODE == 0) ? g_xn_lo : g_ao_lo;
    const __nv_bfloat16* __restrict__ Bh = (MODE == 0) ? g_wq_hi : g_wo_hi;
    const __nv_bfloat16* __restrict__ Bl = (MODE == 0) ? g_wq_lo : g_wo_lo;

    float c[2][8][4] = {};

    gemm_load(sb, 0, Ah, Al, Bh, Bl, m0, n0, K, 0, tid);
    CP_COMMIT();

    for (int cc = 0; cc < NC; cc++) {
        __syncthreads();                      // prior compute done with buf (cc+1)&1
        if (cc + 1 < NC)
            gemm_load(sb, (cc + 1) & 1, Ah, Al, Bh, Bl, m0, n0, K, (cc + 1) * 32, tid);
        CP_COMMIT();
        CP_WAIT1();                           // group cc complete
        __syncthreads();

        const uint32_t uAh = sb + (cc & 1) * GST;
        const uint32_t uAl = uAh + 10240;
        const uint32_t uBh = uAh + 20480;
        const uint32_t uBl = uAh + 30720;

        #pragma unroll
        for (int hh = 0; hh < 2; hh++) {
            const int acb = hh * 32 + (lane >> 4) * 16;
            uint32_t ah[2][4], al[2][4];
            #pragma unroll
            for (int i = 0; i < 2; i++) {
                const uint32_t ro = (uint32_t)((wm + i * 16 + (lane & 15)) * 80 + acb);
                ldsm4(ah[i], uAh + ro);
                ldsm4(al[i], uAl + ro);
            }
            #pragma unroll
            for (int nb = 0; nb < 4; nb++) {
                uint32_t bhh[4], bll[4];
                const uint32_t ro = (uint32_t)((wn + nb * 16 + (lane & 7)
                                   + ((lane >> 3) & 1) * 8) * 80 + acb);
                ldsm4(bhh, uBh + ro);
                ldsm4(bll, uBl + ro);
                #pragma unroll
                for (int i = 0; i < 2; i++) {
                    mma16816(c[i][nb*2+0], ah[i], bhh[0], bhh[2]);
                    mma16816(c[i][nb*2+1], ah[i], bhh[1], bhh[3]);
                    mma16816(c[i][nb*2+0], ah[i], bll[0], bll[2]);
                    mma16816(c[i][nb*2+1], ah[i], bll[1], bll[3]);
                    mma16816(c[i][nb*2+0], al[i], bhh[0], bhh[2]);
                    mma16816(c[i][nb*2+1], al[i], bhh[1], bhh[3]);
                }
            }
        }
    }

    if (MODE == 0) {
        #pragma unroll
        for (int i = 0; i < 2; i++) {
            const int r0g = m0 + wm + i * 16 + g;
            #pragma unroll
            for (int j = 0; j < 8; j++) {
                const int col  = n0 + wn + j * 8 + tig * 2;
                const int part = col >> 9;
                const int hd   = (col >> 6) & 7;
                const int d    = col & 63;
                __nv_bfloat16* dh_ = (part == 0) ? g_qh : ((part == 1) ? g_kh : g_vh);
                __nv_bfloat16* dl_ = (part == 0) ? g_ql : ((part == 1) ? g_kl : g_vl);
                const float sc = (part == 0) ? 0.125f : 1.0f;
                #pragma unroll
                for (int rr = 0; rr < 2; rr++) {
                    const int row = r0g + rr * 8;
                    const int bb = row >> 12, seq = row & 4095;
                    const size_t off = (((size_t)(bb * HEADS + hd)) * NSEQ + seq) * DH + d;
                    uint32_t ph, pl;
                    pack_split(c[i][j][rr*2+0] * sc, c[i][j][rr*2+1] * sc, ph, pl);
                    *(uint32_t*)(dh_ + off) = ph;
                    *(uint32_t*)(dl_ + off) = pl;
                }
            }
        }
    } else {
        #pragma unroll
        for (int i = 0; i < 2; i++) {
            const int r0g = m0 + wm + i * 16 + g;
            #pragma unroll
            for (int j = 0; j < 8; j++) {
                const int col = n0 + wn + j * 8 + tig * 2;
                #pragma unroll
                for (int rr = 0; rr < 2; rr++) {
                    const int row = r0g + rr * 8;
                    *(float2*)(Cout + (size_t)row * DIM + col) =
                        make_float2(c[i][j][rr*2+0], c[i][j][rr*2+1]);
                }
            }
        }
    }
}

// ===================== 4) causal flash attention, cp.async 2-stage ===========
// stage (32768 B): KH@0, KL@8192, VH@16384, VL@24576 — 64 rows x 128B swizzled
// Q staged in stage-1 area during prologue. Total dynamic smem 65536.
#define AST 32768
__device__ __forceinline__ void kv_load(uint32_t sb, int st, size_t kvbase,
                                        int kt, int tid) {
    const int r  = tid >> 2;
    const int c0 = (tid & 3) * 2;
    const uint32_t base = sb + st * AST;
    #pragma unroll
    for (int it = 0; it < 2; it++) {
        const int ch = c0 + it;
        const uint32_t d = base + sw128(r, ch * 16);
        const size_t src = kvbase + (size_t)(kt * 64 + r) * DH + ch * 8;
        cp16(d,         g_kh + src);
        cp16(d + 8192,  g_kl + src);
        cp16(d + 16384, g_vh + src);
        cp16(d + 24576, g_vl + src);
    }
}

__global__ void __launch_bounds__(256, 2) attn_kernel() {
    extern __shared__ char dsm[];
    const uint32_t sb = smem_u32(dsm);
    const int qt = (int)gridDim.x - 1 - (int)blockIdx.x;  // big tiles first
    const int bh = blockIdx.y, b = bh >> 3, h = bh & 7;
    const int tid = threadIdx.x, lane = tid & 31, warp = tid >> 5;
    const int g = lane >> 2, tig = lane & 3;
    const int wm = warp * 16;
    const size_t kvbase = (size_t)bh * NSEQ * DH;

    // prefetch kv tile 0 into stage 0 (overlaps Q staging below)
    kv_load(sb, 0, kvbase, 0, tid);
    CP_COMMIT();

    // stage Q into stage-1 area: QH @32768, QL @49152
    const size_t qbase = ((size_t)bh * NSEQ + qt * 128) * DH;
    for (int i = tid; i < 1024; i += 256) {
        const int r = i >> 3, cch = i & 7;
        const uint32_t d = sw128(r, cch * 16);
        const size_t src = qbase + (size_t)r * DH + cch * 8;
        *(uint4*)(dsm + 32768 + d) = *(const uint4*)(g_qh + src);
        *(uint4*)(dsm + 49152 + d) = *(const uint4*)(g_ql + src);
    }
    __syncthreads();
    uint32_t qh[4][4], ql[4][4];
    #pragma unroll
    for (int kk = 0; kk < 4; kk++) {
        const int r  = wm + (lane & 15);
        const int cb = kk * 32 + (lane >> 4) * 16;
        const uint32_t off = sw128(r, cb);
        ldsm4(qh[kk], sb + 32768 + off);
        ldsm4(ql[kk], sb + 49152 + off);
    }

    float o[8][4] = {};
    float m0v = -1e30f, m1v = -1e30f, l0 = 0.f, l1 = 0.f;
    const int ktmax = 2 * qt + 1;

    for (int kt = 0; kt <= ktmax; kt++) {
        __syncthreads();                     // prior compute / Q-frag reads done
        if (kt + 1 <= ktmax)
            kv_load(sb, (kt + 1) & 1, kvbase, kt + 1, tid);
        CP_COMMIT();
        CP_WAIT1();                          // kv tile kt resident
        __syncthreads();

        const uint32_t uK  = sb + (kt & 1) * AST;
        const uint32_t uKl = uK + 8192;
        const uint32_t uV  = uK + 16384;
        const uint32_t uVl = uK + 24576;

        // ---- S = Q K^T (3-term bf16) ----
        float s[8][4] = {};
        #pragma unroll
        for (int kk = 0; kk < 4; kk++) {
            const int cb = kk * 32 + (lane >> 4) * 16;
            #pragma unroll
            for (int nb = 0; nb < 4; nb++) {
                const int r = nb * 16 + (lane & 7) + ((lane >> 3) & 1) * 8;
                const uint32_t off = sw128(r, cb);
                uint32_t kbh[4], kbl[4];
                ldsm4(kbh, uK  + off);
                ldsm4(kbl, uKl + off);
                mma16816(s[nb*2+0], qh[kk], kbh[0], kbh[2]);
                mma16816(s[nb*2+1], qh[kk], kbh[1], kbh[3]);
                mma16816(s[nb*2+0], qh[kk], kbl[0], kbl[2]);
                mma16816(s[nb*2+1], qh[kk], kbl[1], kbl[3]);
                mma16816(s[nb*2+0], ql[kk], kbh[0], kbh[2]);
                mma16816(s[nb*2+1], ql[kk], kbh[1], kbh[3]);
            }
        }
        // ---- causal mask (diagonal tiles only) ----
        if (kt >= 2 * qt) {
            const int row0 = qt * 128 + wm + g;
            #pragma unroll
            for (int j = 0; j < 8; j++) {
                const int col = kt * 64 + j * 8 + tig * 2;
                if (col     > row0)     s[j][0] = -1e30f;
                if (col + 1 > row0)     s[j][1] = -1e30f;
                if (col     > row0 + 8) s[j][2] = -1e30f;
                if (col + 1 > row0 + 8) s[j][3] = -1e30f;
            }
        }
        // ---- online softmax ----
        float mx0 = -1e30f, mx1 = -1e30f;
        #pragma unroll
        for (int j = 0; j < 8; j++) {
            mx0 = fmaxf(mx0, fmaxf(s[j][0], s[j][1]));
            mx1 = fmaxf(mx1, fmaxf(s[j][2], s[j][3]));
        }
        mx0 = fmaxf(mx0, __shfl_xor_sync(0xffffffffu, mx0, 1));
        mx0 = fmaxf(mx0, __shfl_xor_sync(0xffffffffu, mx0, 2));
        mx1 = fmaxf(mx1, __shfl_xor_sync(0xffffffffu, mx1, 1));
        mx1 = fmaxf(mx1, __shfl_xor_sync(0xffffffffu, mx1, 2));
        const float mn0 = fmaxf(m0v, mx0), mn1 = fmaxf(m1v, mx1);
        const float cor0 = __expf(m0v - mn0), cor1 = __expf(m1v - mn1);
        m0v = mn0; m1v = mn1;
        float ls0 = 0.f, ls1 = 0.f;
        #pragma unroll
        for (int j = 0; j < 8; j++) {
            s[j][0] = __expf(s[j][0] - mn0);
            s[j][1] = __expf(s[j][1] - mn0);
            s[j][2] = __expf(s[j][2] - mn1);
            s[j][3] = __expf(s[j][3] - mn1);
            ls0 += s[j][0] + s[j][1];
            ls1 += s[j][2] + s[j][3];
        }
        ls0 += __shfl_xor_sync(0xffffffffu, ls0, 1);
        ls0 += __shfl_xor_sync(0xffffffffu, ls0, 2);
        ls1 += __shfl_xor_sync(0xffffffffu, ls1, 1);
        ls1 += __shfl_xor_sync(0xffffffffu, ls1, 2);
        l0 = l0 * cor0 + ls0;
        l1 = l1 * cor1 + ls1;
        #pragma unroll
        for (int j = 0; j < 8; j++) {
            o[j][0] *= cor0; o[j][1] *= cor0;
            o[j][2] *= cor1; o[j][3] *= cor1;
        }
        // ---- O += P V (3-term bf16) ----
        #pragma unroll
        for (int kk = 0; kk < 4; kk++) {
            uint32_t pah[4], pal[4];
            pack_split(s[2*kk  ][0], s[2*kk  ][1], pah[0], pal[0]);
            pack_split(s[2*kk  ][2], s[2*kk  ][3], pah[1], pal[1]);
            pack_split(s[2*kk+1][0], s[2*kk+1][1], pah[2], pal[2]);
            pack_split(s[2*kk+1][2], s[2*kk+1][3], pah[3], pal[3]);
            #pragma unroll
            for (int nb = 0; nb < 4; nb++) {
                const int r  = kk * 16 + (lane & 7) + ((lane >> 4) << 3);
                const int cb = nb * 32 + ((lane >> 3) & 1) * 16;
                const uint32_t off = sw128(r, cb);
                uint32_t vbh[4], vbl[4];
                ldsm4t(vbh, uV  + off);
                ldsm4t(vbl, uVl + off);
                mma16816(o[nb*2+0], pah, vbh[0], vbh[2]);
                mma16816(o[nb*2+1], pah, vbh[1], vbh[3]);
                mma16816(o[nb*2+0], pah, vbl[0], vbl[2]);
                mma16816(o[nb*2+1], pah, vbl[1], vbl[3]);
                mma16816(o[nb*2+0], pal, vbh[0], vbh[2]);
                mma16816(o[nb*2+1], pal, vbh[1], vbh[3]);
            }
        }
    }

    // ---- epilogue ----
    const float inv0 = 1.0f / (l0 + 1e-10f);
    const float inv1 = 1.0f / (l1 + 1e-10f);
    const int row0 = qt * 128 + wm + g;
    #pragma unroll
    for (int j = 0; j < 8; j++) {
        const int col = h * DH + j * 8 + tig * 2;
        {
            const size_t off = (size_t)(b * NSEQ + row0) * AO_N + col;
            uint32_t ph, pl;
            pack_split(o[j][0] * inv0, o[j][1] * inv0, ph, pl);
            *(uint32_t*)(g_ao_hi + off) = ph;
            *(uint32_t*)(g_ao_lo + off) = pl;
        }
        {
            const size_t off = (size_t)(b * NSEQ + row0 + 8) * AO_N + col;
            uint32_t ph, pl;
            pack_split(o[j][2] * inv1, o[j][3] * inv1, ph, pl);
            *(uint32_t*)(g_ao_hi + off) = ph;
            *(uint32_t*)(g_ao_lo + off) = pl;
        }
    }
}

// ===================== launch ================================================
extern "C" void kernel_launch(void* const* d_in, const int* in_sizes, int n_in,
                              void* d_out, int out_size) {
    const float* x     = (const float*)d_in[0];
    const float* gamma = (const float*)d_in[1];
    const float* beta  = (const float*)d_in[2];
    const float* wqkv  = (const float*)d_in[3];
    const float* wout  = (const float*)d_in[4];
    float* out = (float*)d_out;

    cudaFuncSetAttribute(gemm_mma<0>, cudaFuncAttributeMaxDynamicSharedMemorySize, 2 * GST);
    cudaFuncSetAttribute(gemm_mma<1>, cudaFuncAttributeMaxDynamicSharedMemorySize, 2 * GST);
    cudaFuncSetAttribute(attn_kernel, cudaFuncAttributeMaxDynamicSharedMemorySize, 2 * AST);

    ln_kernel<<<TOKENS, 256>>>(x, gamma, beta);
    conv_w<0><<<dim3(QKV_N / 32, DIM / 32), dim3(32, 8)>>>(wqkv);
    conv_w<1><<<dim3(DIM / 32, AO_N / 32), dim3(32, 8)>>>(wout);
    gemm_mma<0><<<dim3(QKV_N / 128, TOKENS / 128), 256, 2 * GST>>>(nullptr);
    attn_kernel<<<dim3(NSEQ / 128, BH_N), 256, 2 * AST>>>();
    gemm_mma<1><<<dim3(DIM / 128, TOKENS / 128), 256, 2 * GST>>>(out);
}